// round 15
// baseline (speedup 1.0000x reference)
#include <cuda_runtime.h>
#include <cuda_bf16.h>
#include <stdint.h>

// Problem constants
#define B_    4096
#define T_    80
#define EMB   100
#define EMBP  128
#define UNITS 512
#define NCOL  2048

// ---------------- device scratch ----------------
__device__ float g_m0[4 * B_ * EMB];
__device__ __nv_bfloat16 g_m1p[4 * B_ * UNITS];  // packed [cell][4 gates]
__device__ __nv_bfloat16 g_xm[(size_t)T_ * 4 * B_ * EMBP]; // [t][g][b][k]
__device__ float g_c0[B_ * UNITS];
__device__ float g_c1[B_ * UNITS];
__device__ __nv_bfloat16 g_h0b[2][B_ * UNITS];
__device__ __nv_bfloat16 g_h1b[2][B_ * UNITS];
__device__ __nv_bfloat16 g_h0m[4 * B_ * UNITS];
// precomputed layer0 x-part pre-activations, bf16, [t][b][n'] (gate-blocked cols)
__device__ __nv_bfloat16 g_zx[(size_t)T_ * B_ * NCOL];
// bf16 weights, transposed + gate-blocked: n' = (u/32)*128 + g*32 + (u%32)
__device__ __nv_bfloat16 g_wt0[NCOL * EMBP];
__device__ __nv_bfloat16 g_ut0[NCOL * UNITS];
__device__ __nv_bfloat16 g_wt1[NCOL * UNITS];
__device__ __nv_bfloat16 g_ut1[NCOL * UNITS];

// ---------------- threefry2x32 (full 20 rounds) ----------------
__device__ __forceinline__ uint32_t rotl32(uint32_t x, int d) {
    return (x << d) | (x >> (32 - d));
}

__device__ __forceinline__ void tf2x32(uint32_t k0, uint32_t k1,
                                       uint32_t x0, uint32_t x1,
                                       uint32_t& o0, uint32_t& o1) {
    uint32_t ks0 = k0, ks1 = k1, ks2 = k0 ^ k1 ^ 0x1BD11BDAu;
    x0 += ks0; x1 += ks1;
#define TF_RND(r) { x0 += x1; x1 = rotl32(x1, r); x1 ^= x0; }
    TF_RND(13) TF_RND(15) TF_RND(26) TF_RND(6)
    x0 += ks1; x1 += ks2 + 1u;
    TF_RND(17) TF_RND(29) TF_RND(16) TF_RND(24)
    x0 += ks2; x1 += ks0 + 2u;
    TF_RND(13) TF_RND(15) TF_RND(26) TF_RND(6)
    x0 += ks0; x1 += ks1 + 3u;
    TF_RND(17) TF_RND(29) TF_RND(16) TF_RND(24)
    x0 += ks1; x1 += ks2 + 4u;
    TF_RND(13) TF_RND(15) TF_RND(26) TF_RND(6)
    x0 += ks2; x1 += ks0 + 5u;
#undef TF_RND
    o0 = x0; o1 = x1;
}

__device__ __forceinline__ float bits_to_mask(uint32_t bits) {
    float u = __uint_as_float((bits >> 9) | 0x3f800000u) - 1.0f;
    return (u < 0.8f) ? (1.0f / 0.8f) : 0.0f;
}

#define S0_ (4 * B_ * EMB)
#define S1_ (4 * B_ * UNITS)
#define S2_ (B_ * UNITS)

__global__ void setup_kernel() {
    size_t idx = (size_t)blockIdx.x * blockDim.x + threadIdx.x;
    if (idx < S0_) {
        uint32_t a0, a1, o0, o1;
        tf2x32(0u, 42u, 0u, 0u, a0, a1);
        tf2x32(a0, a1, 0u, (uint32_t)idx, o0, o1);
        g_m0[idx] = bits_to_mask(o0 ^ o1);
    } else if (idx < (size_t)S0_ + S1_) {
        uint32_t b0, b1, o0, o1;
        uint32_t j = (uint32_t)(idx - S0_);   // [g][b][u] flattened counter
        tf2x32(0u, 42u, 0u, 1u, b0, b1);
        tf2x32(b0, b1, 0u, j, o0, o1);
        uint32_t g = j >> 21;                 // B_*UNITS = 2^21
        uint32_t i = j & 0x1FFFFFu;
        g_m1p[(size_t)i * 4 + g] = __float2bfloat16(bits_to_mask(o0 ^ o1));
    } else if (idx < (size_t)S0_ + S1_ + S2_) {
        int j = (int)(idx - S0_ - S1_);
        g_c0[j] = 0.f; g_c1[j] = 0.f;
        __nv_bfloat16 zb = __float2bfloat16(0.f);
        g_h0b[0][j] = zb; g_h1b[0][j] = zb;
    }
}

// ---------------- precompute x*m0 in bf16: [t][g][b][k] ----------------
__global__ void xm_kernel(const int* __restrict__ inputs,
                          const float* __restrict__ embed) {
    size_t idx = (size_t)blockIdx.x * blockDim.x + threadIdx.x;
    if (idx >= (size_t)T_ * 4 * B_ * EMBP) return;
    int k = (int)(idx & 127);
    int b = (int)((idx >> 7) & 4095);
    int g = (int)((idx >> 19) & 3);
    int t = (int)(idx >> 21);
    float v = 0.f;
    if (k < EMB) {
        int tok = inputs[b * T_ + t];
        v = embed[(size_t)tok * EMB + k] * g_m0[((size_t)g * B_ + b) * EMB + k];
    }
    g_xm[idx] = __float2bfloat16(v);
}

// ---------------- weight transpose + bf16 + gate-blocked reorder -----------
#define WT0_N ((size_t)NCOL * EMBP)
#define WTU_N ((size_t)NCOL * UNITS)

__global__ void wtrans_all(const float* __restrict__ W0,
                           const float* __restrict__ U0,
                           const float* __restrict__ W1,
                           const float* __restrict__ U1) {
    size_t idx = (size_t)blockIdx.x * blockDim.x + threadIdx.x;
    if (idx < WT0_N) {
        int k  = (int)(idx & 127);
        int np = (int)(idx >> 7);
        int g = (np >> 5) & 3, ul = np & 31, j = np >> 7;
        int csrc = g * 512 + j * 32 + ul;
        float v = (k < EMB) ? W0[(size_t)k * NCOL + csrc] : 0.f;
        g_wt0[idx] = __float2bfloat16(v);
        return;
    }
    size_t r = idx - WT0_N;
    if (r >= 3 * WTU_N) return;
    int sel = (int)(r / WTU_N);
    size_t jdx = r - (size_t)sel * WTU_N;
    int k  = (int)(jdx & 511);
    int np = (int)(jdx >> 9);
    int g = (np >> 5) & 3, ul = np & 31, j = np >> 7;
    int csrc = g * 512 + j * 32 + ul;
    const float* src = (sel == 0) ? U0 : (sel == 1) ? W1 : U1;
    __nv_bfloat16* dst = (sel == 0) ? g_ut0 : (sel == 1) ? g_wt1 : g_ut1;
    dst[jdx] = __float2bfloat16(src[(size_t)k * NCOL + csrc]);
}

// ---------------- shared GEMM machinery ----------------
#define KC2    64
#define ASTR   144
#define APLANE (128 * ASTR)        // 18432
#define ABYTES (4 * APLANE)        // 73728
#define BBYTES (256 * ASTR)        // 36864
#define STAGE  (ABYTES + BBYTES)   // 110592
#define SMEMSZ (2 * STAGE)         // 221184

__device__ __forceinline__ void cpasync16(uint32_t dst, const void* src) {
    asm volatile("cp.async.cg.shared.global [%0], [%1], 16;"
                 :: "r"(dst), "l"(src) : "memory");
}

__device__ __forceinline__ void ldmatrix4(uint32_t& r0, uint32_t& r1,
                                          uint32_t& r2, uint32_t& r3,
                                          uint32_t addr) {
    asm volatile("ldmatrix.sync.aligned.m8n8.x4.shared.b16 {%0,%1,%2,%3}, [%4];"
                 : "=r"(r0), "=r"(r1), "=r"(r2), "=r"(r3) : "r"(addr));
}

__device__ __forceinline__ void mma_bf16(float* c, uint32_t a0, uint32_t a1,
                                         uint32_t a2, uint32_t a3,
                                         uint32_t b0, uint32_t b1) {
    asm volatile(
        "mma.sync.aligned.m16n8k16.row.col.f32.bf16.bf16.f32 "
        "{%0,%1,%2,%3}, {%4,%5,%6,%7}, {%8,%9}, {%0,%1,%2,%3};"
        : "+f"(c[0]), "+f"(c[1]), "+f"(c[2]), "+f"(c[3])
        : "r"(a0), "r"(a1), "r"(a2), "r"(a3), "r"(b0), "r"(b1));
}

__device__ __forceinline__ float tanh_ap(float x) {
    float r;
    asm("tanh.approx.f32 %0, %1;" : "=f"(r) : "f"(x));
    return r;
}
__device__ __forceinline__ float sig_ap(float x) {
    return 0.5f * tanh_ap(0.5f * x) + 0.5f;
}

// ---------------- upfront layer0 x-GEMM over all T ----------------
// grid (8 n-tiles, 32 m-tiles, 80 t), 512 thr, K = EMBP (2 chunks of 64).
// Output zx[t][b][n'] bf16, gate-blocked columns.
__global__ __launch_bounds__(512, 1)
void x0_gemm(const __nv_bfloat16* __restrict__ xm,   // [t][g][b][k]
             const __nv_bfloat16* __restrict__ wt0)  // [2048][EMBP]
{
    extern __shared__ char dsm[];
    uint32_t smem_base;
    asm("{ .reg .u64 t; cvta.to.shared.u64 t, %1; cvt.u32.u64 %0, t; }"
        : "=r"(smem_base) : "l"(dsm));

    const int tid  = threadIdx.x;
    const int wid  = tid >> 5;
    const int lane = tid & 31;
    const int wm   = wid >> 3;
    const int jsub = (wid >> 2) & 1;
    const int gate = wid & 3;
    const int gq   = lane >> 2;
    const int gt   = lane & 3;
    const int arow = lane & 7;
    const int asel = lane >> 3;

    const int m0v = blockIdx.y * 128;
    const int n0  = blockIdx.x * 256;
    const int t   = blockIdx.z;
    const __nv_bfloat16* a1 = xm + (size_t)t * 4 * B_ * EMBP;

    float acc[4][4][4];
#pragma unroll
    for (int mt = 0; mt < 4; mt++)
#pragma unroll
        for (int nt = 0; nt < 4; nt++)
#pragma unroll
            for (int e = 0; e < 4; e++) acc[mt][nt][e] = 0.f;

    auto issue = [&](int ic, int buf) {
        const uint32_t base = smem_base + buf * STAGE;
#pragma unroll
        for (int i = 0; i < 8; i++) {
            int s = tid + i * 512;
            int p = s >> 10, r = (s >> 3) & 127, sg = s & 7;
            cpasync16(base + p * APLANE + r * ASTR + sg * 16,
                      (const char*)(a1 + (size_t)p * B_ * EMBP
                                    + (size_t)(m0v + r) * EMBP
                                    + (size_t)ic * KC2) + sg * 16);
        }
#pragma unroll
        for (int i = 0; i < 4; i++) {
            int s = tid + i * 512;
            int r = s >> 3, sg = s & 7;
            cpasync16(base + ABYTES + r * ASTR + sg * 16,
                      (const char*)(wt0 + (size_t)(n0 + r) * EMBP
                                    + (size_t)ic * KC2) + sg * 16);
        }
    };

    auto compute = [&](int buf) {
        const uint32_t stg = smem_base + buf * STAGE;
        const uint32_t plane_off = (uint32_t)(gate * APLANE);
#pragma unroll
        for (int ks = 0; ks < 4; ks++) {
            uint32_t bfr[4][2];
#pragma unroll
            for (int ntp = 0; ntp < 2; ntp++) {
                uint32_t r0, r1, r2, r3;
                ldmatrix4(r0, r1, r2, r3,
                    stg + ABYTES
                        + (uint32_t)((jsub * 128 + gate * 32 + ntp * 16
                                      + (asel >> 1) * 8 + arow) * ASTR)
                        + (uint32_t)((ks * 16 + (asel & 1) * 8) * 2));
                bfr[2 * ntp][0] = r0; bfr[2 * ntp][1] = r1;
                bfr[2 * ntp + 1][0] = r2; bfr[2 * ntp + 1][1] = r3;
            }
#pragma unroll
            for (int mt = 0; mt < 4; mt++) {
                uint32_t a0r, a1r, a2r, a3r;
                ldmatrix4(a0r, a1r, a2r, a3r,
                    stg + plane_off
                        + (uint32_t)((wm * 64 + mt * 16 + (asel & 1) * 8 + arow) * ASTR)
                        + (uint32_t)((ks * 16 + (asel >> 1) * 8) * 2));
#pragma unroll
                for (int nt = 0; nt < 4; nt++)
                    mma_bf16(acc[mt][nt], a0r, a1r, a2r, a3r,
                             bfr[nt][0], bfr[nt][1]);
            }
        }
    };

    issue(0, 0);
    asm volatile("cp.async.commit_group;" ::: "memory");
    issue(1, 1);
    asm volatile("cp.async.commit_group;" ::: "memory");
    asm volatile("cp.async.wait_group 1;" ::: "memory");
    __syncthreads();
    compute(0);
    asm volatile("cp.async.wait_group 0;" ::: "memory");
    __syncthreads();
    compute(1);
    __syncthreads();

    // acc -> smem z tile [128][260] fp32
    float* zs = (float*)dsm;
#pragma unroll
    for (int mt = 0; mt < 4; mt++) {
        int row0 = wm * 64 + mt * 16 + gq;
#pragma unroll
        for (int nt = 0; nt < 4; nt++) {
            int col = jsub * 128 + gate * 32 + nt * 8 + gt * 2;
            zs[row0 * 260 + col]     = acc[mt][nt][0];
            zs[row0 * 260 + col + 1] = acc[mt][nt][1];
            zs[(row0 + 8) * 260 + col]     = acc[mt][nt][2];
            zs[(row0 + 8) * 260 + col + 1] = acc[mt][nt][3];
        }
    }
    __syncthreads();

    // zs -> zx bf16, coalesced
#pragma unroll 8
    for (int i = 0; i < 32; i++) {
        int p = i * 512 + tid;            // 0..16383 pairs
        int row = p >> 7;
        int cp  = (p & 127) << 1;
        __nv_bfloat162 v = __floats2bfloat162_rn(zs[row * 260 + cp],
                                                 zs[row * 260 + cp + 1]);
        *(__nv_bfloat162*)(g_zx + ((size_t)t * B_ + m0v + row) * NCOL + n0 + cp) = v;
    }
}

// ---------------- fused gate GEMM + LSTM cell epilogue ----------------
__global__ __launch_bounds__(512, 1)
void gate_gemm_fused(const __nv_bfloat16* __restrict__ a1, int k1, int nch1,
                     size_t plane_stride,
                     const __nv_bfloat16* __restrict__ a2,   // h prev [B][512]
                     const __nv_bfloat16* __restrict__ bt1,  // [2048][k1]
                     const __nv_bfloat16* __restrict__ bt2,  // [2048][512]
                     const float* __restrict__ bias,
                     float* __restrict__ cst,
                     __nv_bfloat16* __restrict__ hout,
                     __nv_bfloat16* __restrict__ hmout,      // null for layer1
                     const __nv_bfloat16* __restrict__ m1p,  // packed [cell][4]
                     const __nv_bfloat16* __restrict__ zx)   // [b][2048] or null
{
    extern __shared__ char dsm[];
    uint32_t smem_base;
    asm("{ .reg .u64 t; cvta.to.shared.u64 t, %1; cvt.u32.u64 %0, t; }"
        : "=r"(smem_base) : "l"(dsm));

    const int tid  = threadIdx.x;
    const int wid  = tid >> 5;
    const int lane = tid & 31;
    const int wm   = wid >> 3;
    const int jsub = (wid >> 2) & 1;
    const int gate = wid & 3;
    const int gq   = lane >> 2;
    const int gt   = lane & 3;
    const int arow = lane & 7;
    const int asel = lane >> 3;

    const int m0v = blockIdx.y * 128;
    const int n0  = blockIdx.x * 256;
    const int u0  = blockIdx.x * 64;

    const int ncht = nch1 + UNITS / KC2;

    float acc[4][4][4];
#pragma unroll
    for (int mt = 0; mt < 4; mt++)
#pragma unroll
        for (int nt = 0; nt < 4; nt++)
#pragma unroll
            for (int e = 0; e < 4; e++) acc[mt][nt][e] = 0.f;

    auto issue = [&](int ic, int buf) {
        const uint32_t base = smem_base + buf * STAGE;
        if (ic < nch1) {
#pragma unroll
            for (int i = 0; i < 8; i++) {
                int s = tid + i * 512;
                int p = s >> 10, r = (s >> 3) & 127, sg = s & 7;
                cpasync16(base + p * APLANE + r * ASTR + sg * 16,
                          (const char*)(a1 + (size_t)p * plane_stride
                                        + (size_t)(m0v + r) * k1
                                        + (size_t)ic * KC2) + sg * 16);
            }
#pragma unroll
            for (int i = 0; i < 4; i++) {
                int s = tid + i * 512;
                int r = s >> 3, sg = s & 7;
                cpasync16(base + ABYTES + r * ASTR + sg * 16,
                          (const char*)(bt1 + (size_t)(n0 + r) * k1
                                        + (size_t)ic * KC2) + sg * 16);
            }
        } else {
            int ic2 = ic - nch1;
#pragma unroll
            for (int i = 0; i < 2; i++) {
                int s = tid + i * 512;
                int r = s >> 3, sg = s & 7;
                cpasync16(base + r * ASTR + sg * 16,
                          (const char*)(a2 + (size_t)(m0v + r) * UNITS
                                        + (size_t)ic2 * KC2) + sg * 16);
            }
#pragma unroll
            for (int i = 0; i < 4; i++) {
                int s = tid + i * 512;
                int r = s >> 3, sg = s & 7;
                cpasync16(base + ABYTES + r * ASTR + sg * 16,
                          (const char*)(bt2 + (size_t)(n0 + r) * UNITS
                                        + (size_t)ic2 * KC2) + sg * 16);
            }
        }
    };

    issue(0, 0);
    asm volatile("cp.async.commit_group;" ::: "memory");

    for (int ic = 0; ic < ncht; ++ic) {
        const int buf = ic & 1;
        if (ic + 1 < ncht) {
            issue(ic + 1, buf ^ 1);
            asm volatile("cp.async.commit_group;" ::: "memory");
            asm volatile("cp.async.wait_group 1;" ::: "memory");
        } else {
            asm volatile("cp.async.wait_group 0;" ::: "memory");
        }
        __syncthreads();

        const uint32_t stg = smem_base + buf * STAGE;
        const uint32_t plane_off = (ic < nch1) ? (uint32_t)(gate * APLANE) : 0u;

#pragma unroll
        for (int ks = 0; ks < 4; ks++) {
            uint32_t bfr[4][2];
#pragma unroll
            for (int ntp = 0; ntp < 2; ntp++) {
                uint32_t r0, r1, r2, r3;
                ldmatrix4(r0, r1, r2, r3,
                    stg + ABYTES
                        + (uint32_t)((jsub * 128 + gate * 32 + ntp * 16
                                      + (asel >> 1) * 8 + arow) * ASTR)
                        + (uint32_t)((ks * 16 + (asel & 1) * 8) * 2));
                bfr[2 * ntp][0] = r0; bfr[2 * ntp][1] = r1;
                bfr[2 * ntp + 1][0] = r2; bfr[2 * ntp + 1][1] = r3;
            }
#pragma unroll
            for (int mt = 0; mt < 4; mt++) {
                uint32_t a0r, a1r, a2r, a3r;
                ldmatrix4(a0r, a1r, a2r, a3r,
                    stg + plane_off
                        + (uint32_t)((wm * 64 + mt * 16 + (asel & 1) * 8 + arow) * ASTR)
                        + (uint32_t)((ks * 16 + (asel >> 1) * 8) * 2));
#pragma unroll
                for (int nt = 0; nt < 4; nt++)
                    mma_bf16(acc[mt][nt], a0r, a1r, a2r, a3r,
                             bfr[nt][0], bfr[nt][1]);
            }
        }
        __syncthreads();
    }

    // ---- epilogue 1: acc -> smem z tile [128][260] fp32 ----
    float* zs = (float*)dsm;
#pragma unroll
    for (int mt = 0; mt < 4; mt++) {
        int row0 = wm * 64 + mt * 16 + gq;
#pragma unroll
        for (int nt = 0; nt < 4; nt++) {
            int col = jsub * 128 + gate * 32 + nt * 8 + gt * 2;
            zs[row0 * 260 + col]     = acc[mt][nt][0];
            zs[row0 * 260 + col + 1] = acc[mt][nt][1];
            zs[(row0 + 8) * 260 + col]     = acc[mt][nt][2];
            zs[(row0 + 8) * 260 + col + 1] = acc[mt][nt][3];
        }
    }
    __syncthreads();

    // ---- epilogue 2: LSTM cell update for 128 b x 64 u ----
#pragma unroll 4
    for (int pass = 0; pass < 16; pass++) {
        int cell = pass * 512 + tid;
        int bl   = cell >> 6;
        int uloc = cell & 63;
        int js   = uloc >> 5;
        int ul   = uloc & 31;
        int cbase = js * 128 + ul;
        float zi = zs[bl * 260 + cbase]      + bias[u0 + uloc];
        float zf = zs[bl * 260 + cbase + 32] + bias[512 + u0 + uloc];
        float zg = zs[bl * 260 + cbase + 64] + bias[1024 + u0 + uloc];
        float zo = zs[bl * 260 + cbase + 96] + bias[1536 + u0 + uloc];
        if (zx) {
            const __nv_bfloat16* zr = zx + (size_t)(m0v + bl) * NCOL + n0 + cbase;
            zi += __bfloat162float(zr[0]);
            zf += __bfloat162float(zr[32]);
            zg += __bfloat162float(zr[64]);
            zo += __bfloat162float(zr[96]);
        }
        float ig = sig_ap(zi);
        float fg = sig_ap(zf);
        float gg = tanh_ap(zg);
        float og = sig_ap(zo);
        size_t idx = (size_t)(m0v + bl) * UNITS + u0 + uloc;
        float cn = fg * cst[idx] + ig * gg;
        cst[idx] = cn;
        float hn = og * tanh_ap(cn);
        hout[idx] = __float2bfloat16(hn);
        if (hmout) {
            uint2 mv = *(const uint2*)(m1p + (idx << 2));
            __nv_bfloat162 m01 = *reinterpret_cast<__nv_bfloat162*>(&mv.x);
            __nv_bfloat162 m23 = *reinterpret_cast<__nv_bfloat162*>(&mv.y);
            hmout[idx] = __float2bfloat16(hn * __bfloat162float(m01.x));
            hmout[(size_t)B_ * UNITS + idx] =
                __float2bfloat16(hn * __bfloat162float(m01.y));
            hmout[(size_t)2 * B_ * UNITS + idx] =
                __float2bfloat16(hn * __bfloat162float(m23.x));
            hmout[(size_t)3 * B_ * UNITS + idx] =
                __float2bfloat16(hn * __bfloat162float(m23.y));
        }
    }
}

// ---------------- final projection (reads bf16 h1) ----------------
__global__ void out_kernel(const float* __restrict__ Wout,
                           const float* __restrict__ bout,
                           float* __restrict__ out) {
    int warps_per_block = blockDim.x / 32;
    int b = blockIdx.x * warps_per_block + (threadIdx.x >> 5);
    int lane = threadIdx.x & 31;
    if (b >= B_) return;
    float s = 0.f;
    for (int k = lane; k < UNITS; k += 32)
        s += __bfloat162float(g_h1b[0][b * UNITS + k]) * Wout[k];
#pragma unroll
    for (int off = 16; off; off >>= 1)
        s += __shfl_down_sync(0xffffffffu, s, off);
    if (lane == 0)
        out[b] = 1.0f / (1.0f + expf(-(s + bout[0])));
}

// ---------------- launch ----------------
extern "C" void kernel_launch(void* const* d_in, const int* in_sizes, int n_in,
                              void* d_out, int out_size) {
    const int*   inputs = (const int*)  d_in[0];
    const float* embed  = (const float*)d_in[1];
    const float* W0     = (const float*)d_in[2];
    const float* U0     = (const float*)d_in[3];
    const float* b0     = (const float*)d_in[4];
    const float* W1     = (const float*)d_in[5];
    const float* U1     = (const float*)d_in[6];
    const float* b1     = (const float*)d_in[7];
    const float* Wout   = (const float*)d_in[8];
    const float* bout   = (const float*)d_in[9];
    float* out = (float*)d_out;

    float *c0p, *c1p;
    __nv_bfloat16 *xmp, *h0mp, *m1pp, *wt0p, *ut0p, *wt1p, *ut1p, *zxp;
    __nv_bfloat16 (*h0bp)[B_ * UNITS], (*h1bp)[B_ * UNITS];
    cudaGetSymbolAddress((void**)&c0p,  g_c0);
    cudaGetSymbolAddress((void**)&c1p,  g_c1);
    cudaGetSymbolAddress((void**)&xmp,  g_xm);
    cudaGetSymbolAddress((void**)&h0bp, g_h0b);
    cudaGetSymbolAddress((void**)&h1bp, g_h1b);
    cudaGetSymbolAddress((void**)&h0mp, g_h0m);
    cudaGetSymbolAddress((void**)&m1pp, g_m1p);
    cudaGetSymbolAddress((void**)&zxp,  g_zx);
    cudaGetSymbolAddress((void**)&wt0p, g_wt0);
    cudaGetSymbolAddress((void**)&ut0p, g_ut0);
    cudaGetSymbolAddress((void**)&wt1p, g_wt1);
    cudaGetSymbolAddress((void**)&ut1p, g_ut1);

    cudaFuncSetAttribute(gate_gemm_fused,
                         cudaFuncAttributeMaxDynamicSharedMemorySize, SMEMSZ);
    cudaFuncSetAttribute(x0_gemm,
                         cudaFuncAttributeMaxDynamicSharedMemorySize, SMEMSZ);

    {
        size_t tot = (size_t)S0_ + S1_ + S2_;
        setup_kernel<<<(unsigned)((tot + 255) / 256), 256>>>();
    }
    {
        size_t tot = (size_t)T_ * 4 * B_ * EMBP;
        xm_kernel<<<(unsigned)((tot + 255) / 256), 256>>>(inputs, embed);
    }
    {
        size_t tot = WT0_N + 3 * WTU_N;
        wtrans_all<<<(unsigned)((tot + 255) / 256), 256>>>(W0, U0, W1, U1);
    }
    // upfront layer0 x-part GEMM for all timesteps
    {
        dim3 xg(8, 32, T_);
        x0_gemm<<<xg, 512, SMEMSZ>>>(xmp, wt0p);
    }

    dim3 ggrid(8, 32);

    for (int t = 0; t < T_; ++t) {
        int rp = t & 1, wp = rp ^ 1;
        // layer 0: h-part only (K=512) + precomputed zx in epilogue
        gate_gemm_fused<<<ggrid, 512, SMEMSZ>>>(
            xmp, EMBP, 0, (size_t)B_ * EMBP,
            h0bp[rp], wt0p, ut0p, b0,
            c0p, h0bp[wp], h0mp, m1pp,
            zxp + (size_t)t * B_ * NCOL);
        // layer 1: x = 4-plane masked h0 (K=512), h = h1[rp]
        gate_gemm_fused<<<ggrid, 512, SMEMSZ>>>(
            h0mp, UNITS, UNITS / KC2, (size_t)B_ * UNITS,
            h1bp[rp], wt1p, ut1p, b1,
            c1p, h1bp[wp], (__nv_bfloat16*)nullptr,
            (const __nv_bfloat16*)nullptr, (const __nv_bfloat16*)nullptr);
    }

    out_kernel<<<B_ / 8, 256>>>(Wout, bout, out);
}

// round 16
// speedup vs baseline: 1.1084x; 1.1084x over previous
#include <cuda_runtime.h>
#include <cuda_bf16.h>
#include <stdint.h>

// Problem constants
#define B_    4096
#define T_    80
#define EMB   100
#define EMBP  128
#define UNITS 512
#define NCOL  2048

// ---------------- device scratch ----------------
__device__ float g_m0[4 * B_ * EMB];
__device__ __nv_bfloat16 g_m1p[4 * B_ * UNITS];  // packed [cell][4 gates]
__device__ __nv_bfloat16 g_xm[(size_t)T_ * 4 * B_ * EMBP]; // [t][g][b][k]
__device__ float g_c0[B_ * UNITS];
__device__ float g_c1[B_ * UNITS];
__device__ __nv_bfloat16 g_h0b[2][B_ * UNITS];
__device__ __nv_bfloat16 g_h1b[2][B_ * UNITS];
__device__ __nv_bfloat16 g_h0m[2][4 * B_ * UNITS];  // ping-pong masked h0
// bf16 weights, transposed + gate-blocked: n' = (u/32)*128 + g*32 + (u%32)
__device__ __nv_bfloat16 g_wt0[NCOL * EMBP];
__device__ __nv_bfloat16 g_ut0[NCOL * UNITS];
__device__ __nv_bfloat16 g_wt1[NCOL * UNITS];
__device__ __nv_bfloat16 g_ut1[NCOL * UNITS];

// ---------------- threefry2x32 (full 20 rounds) ----------------
__device__ __forceinline__ uint32_t rotl32(uint32_t x, int d) {
    return (x << d) | (x >> (32 - d));
}

__device__ __forceinline__ void tf2x32(uint32_t k0, uint32_t k1,
                                       uint32_t x0, uint32_t x1,
                                       uint32_t& o0, uint32_t& o1) {
    uint32_t ks0 = k0, ks1 = k1, ks2 = k0 ^ k1 ^ 0x1BD11BDAu;
    x0 += ks0; x1 += ks1;
#define TF_RND(r) { x0 += x1; x1 = rotl32(x1, r); x1 ^= x0; }
    TF_RND(13) TF_RND(15) TF_RND(26) TF_RND(6)
    x0 += ks1; x1 += ks2 + 1u;
    TF_RND(17) TF_RND(29) TF_RND(16) TF_RND(24)
    x0 += ks2; x1 += ks0 + 2u;
    TF_RND(13) TF_RND(15) TF_RND(26) TF_RND(6)
    x0 += ks0; x1 += ks1 + 3u;
    TF_RND(17) TF_RND(29) TF_RND(16) TF_RND(24)
    x0 += ks1; x1 += ks2 + 4u;
    TF_RND(13) TF_RND(15) TF_RND(26) TF_RND(6)
    x0 += ks2; x1 += ks0 + 5u;
#undef TF_RND
    o0 = x0; o1 = x1;
}

__device__ __forceinline__ float bits_to_mask(uint32_t bits) {
    float u = __uint_as_float((bits >> 9) | 0x3f800000u) - 1.0f;
    return (u < 0.8f) ? (1.0f / 0.8f) : 0.0f;
}

#define S0_ (4 * B_ * EMB)
#define S1_ (4 * B_ * UNITS)
#define S2_ (B_ * UNITS)

__global__ void setup_kernel() {
    size_t idx = (size_t)blockIdx.x * blockDim.x + threadIdx.x;
    if (idx < S0_) {
        uint32_t a0, a1, o0, o1;
        tf2x32(0u, 42u, 0u, 0u, a0, a1);
        tf2x32(a0, a1, 0u, (uint32_t)idx, o0, o1);
        g_m0[idx] = bits_to_mask(o0 ^ o1);
    } else if (idx < (size_t)S0_ + S1_) {
        uint32_t b0, b1, o0, o1;
        uint32_t j = (uint32_t)(idx - S0_);   // [g][b][u] flattened counter
        tf2x32(0u, 42u, 0u, 1u, b0, b1);
        tf2x32(b0, b1, 0u, j, o0, o1);
        uint32_t g = j >> 21;                 // B_*UNITS = 2^21
        uint32_t i = j & 0x1FFFFFu;
        g_m1p[(size_t)i * 4 + g] = __float2bfloat16(bits_to_mask(o0 ^ o1));
    } else if (idx < (size_t)S0_ + S1_ + S2_) {
        int j = (int)(idx - S0_ - S1_);
        g_c0[j] = 0.f; g_c1[j] = 0.f;
        __nv_bfloat16 zb = __float2bfloat16(0.f);
        g_h0b[0][j] = zb; g_h1b[0][j] = zb;
    }
}

// ---------------- precompute x*m0 in bf16: [t][g][b][k] ----------------
__global__ void xm_kernel(const int* __restrict__ inputs,
                          const float* __restrict__ embed) {
    size_t idx = (size_t)blockIdx.x * blockDim.x + threadIdx.x;
    if (idx >= (size_t)T_ * 4 * B_ * EMBP) return;
    int k = (int)(idx & 127);
    int b = (int)((idx >> 7) & 4095);
    int g = (int)((idx >> 19) & 3);
    int t = (int)(idx >> 21);
    float v = 0.f;
    if (k < EMB) {
        int tok = inputs[b * T_ + t];
        v = embed[(size_t)tok * EMB + k] * g_m0[((size_t)g * B_ + b) * EMB + k];
    }
    g_xm[idx] = __float2bfloat16(v);
}

// ---------------- weight transpose + bf16 + gate-blocked reorder -----------
#define WT0_N ((size_t)NCOL * EMBP)
#define WTU_N ((size_t)NCOL * UNITS)

__global__ void wtrans_all(const float* __restrict__ W0,
                           const float* __restrict__ U0,
                           const float* __restrict__ W1,
                           const float* __restrict__ U1) {
    size_t idx = (size_t)blockIdx.x * blockDim.x + threadIdx.x;
    if (idx < WT0_N) {
        int k  = (int)(idx & 127);
        int np = (int)(idx >> 7);
        int g = (np >> 5) & 3, ul = np & 31, j = np >> 7;
        int csrc = g * 512 + j * 32 + ul;
        float v = (k < EMB) ? W0[(size_t)k * NCOL + csrc] : 0.f;
        g_wt0[idx] = __float2bfloat16(v);
        return;
    }
    size_t r = idx - WT0_N;
    if (r >= 3 * WTU_N) return;
    int sel = (int)(r / WTU_N);
    size_t jdx = r - (size_t)sel * WTU_N;
    int k  = (int)(jdx & 511);
    int np = (int)(jdx >> 9);
    int g = (np >> 5) & 3, ul = np & 31, j = np >> 7;
    int csrc = g * 512 + j * 32 + ul;
    const float* src = (sel == 0) ? U0 : (sel == 1) ? W1 : U1;
    __nv_bfloat16* dst = (sel == 0) ? g_ut0 : (sel == 1) ? g_wt1 : g_ut1;
    dst[jdx] = __float2bfloat16(src[(size_t)k * NCOL + csrc]);
}

// ---------------- shared GEMM machinery ----------------
#define KC2    64
#define ASTR   144
#define APLANE (128 * ASTR)        // 18432
#define ABYTES (4 * APLANE)        // 73728
#define BBYTES (256 * ASTR)        // 36864
#define STAGE  (ABYTES + BBYTES)   // 110592
#define SMEMSZ (2 * STAGE)         // 221184

__device__ __forceinline__ void cpasync16(uint32_t dst, const void* src) {
    asm volatile("cp.async.cg.shared.global [%0], [%1], 16;"
                 :: "r"(dst), "l"(src) : "memory");
}

__device__ __forceinline__ void ldmatrix4(uint32_t& r0, uint32_t& r1,
                                          uint32_t& r2, uint32_t& r3,
                                          uint32_t addr) {
    asm volatile("ldmatrix.sync.aligned.m8n8.x4.shared.b16 {%0,%1,%2,%3}, [%4];"
                 : "=r"(r0), "=r"(r1), "=r"(r2), "=r"(r3) : "r"(addr));
}

__device__ __forceinline__ void mma_bf16(float* c, uint32_t a0, uint32_t a1,
                                         uint32_t a2, uint32_t a3,
                                         uint32_t b0, uint32_t b1) {
    asm volatile(
        "mma.sync.aligned.m16n8k16.row.col.f32.bf16.bf16.f32 "
        "{%0,%1,%2,%3}, {%4,%5,%6,%7}, {%8,%9}, {%0,%1,%2,%3};"
        : "+f"(c[0]), "+f"(c[1]), "+f"(c[2]), "+f"(c[3])
        : "r"(a0), "r"(a1), "r"(a2), "r"(a3), "r"(b0), "r"(b1));
}

__device__ __forceinline__ float tanh_ap(float x) {
    float r;
    asm("tanh.approx.f32 %0, %1;" : "=f"(r) : "f"(x));
    return r;
}
__device__ __forceinline__ float sig_ap(float x) {
    return 0.5f * tanh_ap(0.5f * x) + 0.5f;
}

// ---------------- merged per-step kernel: both layers in one launch --------
// blockIdx.z == 1 : layer0(t)   — x = 4-plane masked embeddings (K=128, 2 ch)
// blockIdx.z == 0 : layer1(t-1) — x = 4-plane masked h0 (K=512, 8 ch)
// Roles are independent (both consume only previous-launch outputs).
// CTA tile 128(b) x 256(n'), 512 thr = 16 warps (2M x 2jsub x 4gates).
__global__ __launch_bounds__(512, 1)
void step_kernel(
    // role z=1 (layer0, step t); a1_0 == null -> role inactive
    const __nv_bfloat16* __restrict__ a1_0,
    const __nv_bfloat16* __restrict__ a2_0,
    float* __restrict__ cst_0,
    __nv_bfloat16* __restrict__ hout_0,
    __nv_bfloat16* __restrict__ hm_0,
    const __nv_bfloat16* __restrict__ m1p,
    const float* __restrict__ bias0,
    // role z=0 (layer1, step t-1); a1_1 == null -> role inactive
    const __nv_bfloat16* __restrict__ a1_1,
    const __nv_bfloat16* __restrict__ a2_1,
    float* __restrict__ cst_1,
    __nv_bfloat16* __restrict__ hout_1,
    const float* __restrict__ bias1)
{
    const bool l0 = (blockIdx.z == 1);
    const __nv_bfloat16* a1 = l0 ? a1_0 : a1_1;
    if (a1 == nullptr) return;

    const int k1   = l0 ? EMBP : UNITS;
    const int nch1 = l0 ? (EMBP / KC2) : (UNITS / KC2);
    const size_t plane_stride = (size_t)B_ * k1;
    const __nv_bfloat16* a2  = l0 ? a2_0 : a2_1;
    const __nv_bfloat16* bt1 = l0 ? g_wt0 : g_wt1;
    const __nv_bfloat16* bt2 = l0 ? g_ut0 : g_ut1;
    const float* bias        = l0 ? bias0 : bias1;
    float* cst               = l0 ? cst_0 : cst_1;
    __nv_bfloat16* hout      = l0 ? hout_0 : hout_1;
    __nv_bfloat16* hmout     = l0 ? hm_0 : nullptr;

    extern __shared__ char dsm[];
    uint32_t smem_base;
    asm("{ .reg .u64 t; cvta.to.shared.u64 t, %1; cvt.u32.u64 %0, t; }"
        : "=r"(smem_base) : "l"(dsm));

    const int tid  = threadIdx.x;
    const int wid  = tid >> 5;
    const int lane = tid & 31;
    const int wm   = wid >> 3;
    const int jsub = (wid >> 2) & 1;
    const int gate = wid & 3;
    const int gq   = lane >> 2;
    const int gt   = lane & 3;
    const int arow = lane & 7;
    const int asel = lane >> 3;

    const int m0v = blockIdx.y * 128;
    const int n0  = blockIdx.x * 256;
    const int u0  = blockIdx.x * 64;

    const int ncht = nch1 + UNITS / KC2;

    float acc[4][4][4];
#pragma unroll
    for (int mt = 0; mt < 4; mt++)
#pragma unroll
        for (int nt = 0; nt < 4; nt++)
#pragma unroll
            for (int e = 0; e < 4; e++) acc[mt][nt][e] = 0.f;

    auto issue = [&](int ic, int buf) {
        const uint32_t base = smem_base + buf * STAGE;
        if (ic < nch1) {
#pragma unroll
            for (int i = 0; i < 8; i++) {
                int s = tid + i * 512;
                int p = s >> 10, r = (s >> 3) & 127, sg = s & 7;
                cpasync16(base + p * APLANE + r * ASTR + sg * 16,
                          (const char*)(a1 + (size_t)p * plane_stride
                                        + (size_t)(m0v + r) * k1
                                        + (size_t)ic * KC2) + sg * 16);
            }
#pragma unroll
            for (int i = 0; i < 4; i++) {
                int s = tid + i * 512;
                int r = s >> 3, sg = s & 7;
                cpasync16(base + ABYTES + r * ASTR + sg * 16,
                          (const char*)(bt1 + (size_t)(n0 + r) * k1
                                        + (size_t)ic * KC2) + sg * 16);
            }
        } else {
            int ic2 = ic - nch1;
#pragma unroll
            for (int i = 0; i < 2; i++) {
                int s = tid + i * 512;
                int r = s >> 3, sg = s & 7;
                cpasync16(base + r * ASTR + sg * 16,
                          (const char*)(a2 + (size_t)(m0v + r) * UNITS
                                        + (size_t)ic2 * KC2) + sg * 16);
            }
#pragma unroll
            for (int i = 0; i < 4; i++) {
                int s = tid + i * 512;
                int r = s >> 3, sg = s & 7;
                cpasync16(base + ABYTES + r * ASTR + sg * 16,
                          (const char*)(bt2 + (size_t)(n0 + r) * UNITS
                                        + (size_t)ic2 * KC2) + sg * 16);
            }
        }
    };

    issue(0, 0);
    asm volatile("cp.async.commit_group;" ::: "memory");

    for (int ic = 0; ic < ncht; ++ic) {
        const int buf = ic & 1;
        if (ic + 1 < ncht) {
            issue(ic + 1, buf ^ 1);
            asm volatile("cp.async.commit_group;" ::: "memory");
            asm volatile("cp.async.wait_group 1;" ::: "memory");
        } else {
            asm volatile("cp.async.wait_group 0;" ::: "memory");
        }
        __syncthreads();

        const uint32_t stg = smem_base + buf * STAGE;
        const uint32_t plane_off = (ic < nch1) ? (uint32_t)(gate * APLANE) : 0u;

#pragma unroll
        for (int ks = 0; ks < 4; ks++) {
            uint32_t bfr[4][2];
#pragma unroll
            for (int ntp = 0; ntp < 2; ntp++) {
                uint32_t r0, r1, r2, r3;
                ldmatrix4(r0, r1, r2, r3,
                    stg + ABYTES
                        + (uint32_t)((jsub * 128 + gate * 32 + ntp * 16
                                      + (asel >> 1) * 8 + arow) * ASTR)
                        + (uint32_t)((ks * 16 + (asel & 1) * 8) * 2));
                bfr[2 * ntp][0] = r0; bfr[2 * ntp][1] = r1;
                bfr[2 * ntp + 1][0] = r2; bfr[2 * ntp + 1][1] = r3;
            }
#pragma unroll
            for (int mt = 0; mt < 4; mt++) {
                uint32_t a0r, a1r, a2r, a3r;
                ldmatrix4(a0r, a1r, a2r, a3r,
                    stg + plane_off
                        + (uint32_t)((wm * 64 + mt * 16 + (asel & 1) * 8 + arow) * ASTR)
                        + (uint32_t)((ks * 16 + (asel >> 1) * 8) * 2));
#pragma unroll
                for (int nt = 0; nt < 4; nt++)
                    mma_bf16(acc[mt][nt], a0r, a1r, a2r, a3r,
                             bfr[nt][0], bfr[nt][1]);
            }
        }
        __syncthreads();
    }

    // ---- epilogue 1: acc -> smem z tile [128][260] fp32 ----
    float* zs = (float*)dsm;
#pragma unroll
    for (int mt = 0; mt < 4; mt++) {
        int row0 = wm * 64 + mt * 16 + gq;
#pragma unroll
        for (int nt = 0; nt < 4; nt++) {
            int col = jsub * 128 + gate * 32 + nt * 8 + gt * 2;
            zs[row0 * 260 + col]     = acc[mt][nt][0];
            zs[row0 * 260 + col + 1] = acc[mt][nt][1];
            zs[(row0 + 8) * 260 + col]     = acc[mt][nt][2];
            zs[(row0 + 8) * 260 + col + 1] = acc[mt][nt][3];
        }
    }
    __syncthreads();

    // ---- epilogue 2: LSTM cell update for 128 b x 64 u ----
#pragma unroll 4
    for (int pass = 0; pass < 16; pass++) {
        int cell = pass * 512 + tid;
        int bl   = cell >> 6;
        int uloc = cell & 63;
        int js   = uloc >> 5;
        int ul   = uloc & 31;
        int cbase = js * 128 + ul;
        float zi = zs[bl * 260 + cbase]      + bias[u0 + uloc];
        float zf = zs[bl * 260 + cbase + 32] + bias[512 + u0 + uloc];
        float zg = zs[bl * 260 + cbase + 64] + bias[1024 + u0 + uloc];
        float zo = zs[bl * 260 + cbase + 96] + bias[1536 + u0 + uloc];
        float ig = sig_ap(zi);
        float fg = sig_ap(zf);
        float gg = tanh_ap(zg);
        float og = sig_ap(zo);
        size_t idx = (size_t)(m0v + bl) * UNITS + u0 + uloc;
        float cn = fg * cst[idx] + ig * gg;
        cst[idx] = cn;
        float hn = og * tanh_ap(cn);
        hout[idx] = __float2bfloat16(hn);
        if (hmout) {
            uint2 mv = *(const uint2*)(m1p + (idx << 2));
            __nv_bfloat162 m01 = *reinterpret_cast<__nv_bfloat162*>(&mv.x);
            __nv_bfloat162 m23 = *reinterpret_cast<__nv_bfloat162*>(&mv.y);
            hmout[idx] = __float2bfloat16(hn * __bfloat162float(m01.x));
            hmout[(size_t)B_ * UNITS + idx] =
                __float2bfloat16(hn * __bfloat162float(m01.y));
            hmout[(size_t)2 * B_ * UNITS + idx] =
                __float2bfloat16(hn * __bfloat162float(m23.x));
            hmout[(size_t)3 * B_ * UNITS + idx] =
                __float2bfloat16(hn * __bfloat162float(m23.y));
        }
    }
}

// ---------------- final projection (reads bf16 h1) ----------------
__global__ void out_kernel(const float* __restrict__ Wout,
                           const float* __restrict__ bout,
                           float* __restrict__ out) {
    int warps_per_block = blockDim.x / 32;
    int b = blockIdx.x * warps_per_block + (threadIdx.x >> 5);
    int lane = threadIdx.x & 31;
    if (b >= B_) return;
    float s = 0.f;
    for (int k = lane; k < UNITS; k += 32)
        s += __bfloat162float(g_h1b[0][b * UNITS + k]) * Wout[k];
#pragma unroll
    for (int off = 16; off; off >>= 1)
        s += __shfl_down_sync(0xffffffffu, s, off);
    if (lane == 0)
        out[b] = 1.0f / (1.0f + expf(-(s + bout[0])));
}

// ---------------- launch ----------------
extern "C" void kernel_launch(void* const* d_in, const int* in_sizes, int n_in,
                              void* d_out, int out_size) {
    const int*   inputs = (const int*)  d_in[0];
    const float* embed  = (const float*)d_in[1];
    const float* W0     = (const float*)d_in[2];
    const float* U0     = (const float*)d_in[3];
    const float* b0     = (const float*)d_in[4];
    const float* W1     = (const float*)d_in[5];
    const float* U1     = (const float*)d_in[6];
    const float* b1     = (const float*)d_in[7];
    const float* Wout   = (const float*)d_in[8];
    const float* bout   = (const float*)d_in[9];
    float* out = (float*)d_out;

    float *c0p, *c1p;
    __nv_bfloat16 *xmp, *m1pp;
    __nv_bfloat16 (*h0bp)[B_ * UNITS], (*h1bp)[B_ * UNITS];
    __nv_bfloat16 (*h0mp)[4 * B_ * UNITS];
    cudaGetSymbolAddress((void**)&c0p,  g_c0);
    cudaGetSymbolAddress((void**)&c1p,  g_c1);
    cudaGetSymbolAddress((void**)&xmp,  g_xm);
    cudaGetSymbolAddress((void**)&h0bp, g_h0b);
    cudaGetSymbolAddress((void**)&h1bp, g_h1b);
    cudaGetSymbolAddress((void**)&h0mp, g_h0m);
    cudaGetSymbolAddress((void**)&m1pp, g_m1p);

    cudaFuncSetAttribute(step_kernel,
                         cudaFuncAttributeMaxDynamicSharedMemorySize, SMEMSZ);

    {
        size_t tot = (size_t)S0_ + S1_ + S2_;
        setup_kernel<<<(unsigned)((tot + 255) / 256), 256>>>();
    }
    {
        size_t tot = (size_t)T_ * 4 * B_ * EMBP;
        xm_kernel<<<(unsigned)((tot + 255) / 256), 256>>>(inputs, embed);
    }
    {
        size_t tot = WT0_N + 3 * WTU_N;
        wtrans_all<<<(unsigned)((tot + 255) / 256), 256>>>(W0, U0, W1, U1);
    }

    dim3 ggrid(8, 32, 2);

    // launch t = 0..T: role z=1 does layer0(t) (skip at t==T),
    //                  role z=0 does layer1(t-1) (skip at t==0).
    for (int t = 0; t <= T_; ++t) {
        const __nv_bfloat16* a1_0 =
            (t < T_) ? (xmp + (size_t)t * 4 * B_ * EMBP) : nullptr;
        const __nv_bfloat16* a2_0 = h0bp[t & 1];
        __nv_bfloat16* hout_0 = h0bp[(t & 1) ^ 1];
        __nv_bfloat16* hm_0   = h0mp[t & 1];

        int s = t - 1;
        const __nv_bfloat16* a1_1 =
            (s >= 0) ? h0mp[s & 1] : nullptr;
        const __nv_bfloat16* a2_1 = h1bp[s & 1];
        __nv_bfloat16* hout_1 = h1bp[(s & 1) ^ 1];

        step_kernel<<<ggrid, 512, SMEMSZ>>>(
            a1_0, a2_0, c0p, hout_0, hm_0, m1pp, b0,
            a1_1, a2_1, c1p, hout_1, b1);
    }

    out_kernel<<<B_ / 8, 256>>>(Wout, bout, out);
}